// round 1
// baseline (speedup 1.0000x reference)
#include <cuda_runtime.h>

#define L_SEQ 1024
#define HID   2048
#define NH    32
#define HD    64
#define FD    64
#define NC    16    // number of chunks
#define CS    64    // chunk size
#define GK    2048
#define GN    2048

// ---------------- scratch (device globals: no allocation allowed) ----------------
__device__ float g_Q [L_SEQ * HID];
__device__ float g_K [L_SEQ * HID];
__device__ float g_V [L_SEQ * HID];
__device__ float g_FQ[NH * L_SEQ * FD];
__device__ float g_FK[NH * L_SEQ * FD];
__device__ float g_S [NH * NC * FD * HD];   // chunk KV sums -> exclusive prefix (in place)
__device__ float g_KS[NH * NC * FD];        // chunk k sums  -> exclusive prefix (in place)
__device__ float g_Y [L_SEQ * HID];         // attention output, [l][h*64+d]

// ---------------- SGEMM: C[M,N] = A[M,K] @ B[N,K]^T  (M=1024, N=K=2048) ----------
// Tiles: BM=128, BN=64, BK=16; 256 threads; 8x4 per-thread microtile.
__global__ __launch_bounds__(256) void sgemm_nt(const float* __restrict__ A,
                                                const float* __restrict__ B,
                                                float* __restrict__ C) {
    __shared__ __align__(16) float As[16 * 132];  // As[k][m], stride 132
    __shared__ __align__(16) float Bs[16 * 68];   // Bs[k][n], stride 68

    int t  = threadIdx.x;
    int m0 = blockIdx.y * 128;
    int n0 = blockIdx.x * 64;
    int tx = t & 15;          // col group (4 cols)
    int ty = t >> 4;          // row group (8 rows)
    int lrow = t >> 2;        // 0..63
    int lseg = (t & 3) << 2;  // k offset 0,4,8,12

    float acc[8][4];
#pragma unroll
    for (int i = 0; i < 8; i++)
#pragma unroll
        for (int j = 0; j < 4; j++) acc[i][j] = 0.f;

    const float* Aptr = A + (long)(m0 + lrow) * GK + lseg;
    const float* Bptr = B + (long)(n0 + lrow) * GK + lseg;

    for (int k0 = 0; k0 < GK; k0 += 16) {
        float4 a0 = *(const float4*)(Aptr + k0);
        float4 a1 = *(const float4*)(Aptr + (long)64 * GK + k0);
        float4 b0 = *(const float4*)(Bptr + k0);

        As[(lseg + 0) * 132 + lrow] = a0.x;
        As[(lseg + 1) * 132 + lrow] = a0.y;
        As[(lseg + 2) * 132 + lrow] = a0.z;
        As[(lseg + 3) * 132 + lrow] = a0.w;
        As[(lseg + 0) * 132 + lrow + 64] = a1.x;
        As[(lseg + 1) * 132 + lrow + 64] = a1.y;
        As[(lseg + 2) * 132 + lrow + 64] = a1.z;
        As[(lseg + 3) * 132 + lrow + 64] = a1.w;
        Bs[(lseg + 0) * 68 + lrow] = b0.x;
        Bs[(lseg + 1) * 68 + lrow] = b0.y;
        Bs[(lseg + 2) * 68 + lrow] = b0.z;
        Bs[(lseg + 3) * 68 + lrow] = b0.w;
        __syncthreads();

#pragma unroll
        for (int kk = 0; kk < 16; kk++) {
            float4 av0 = *(const float4*)&As[kk * 132 + ty * 8];
            float4 av1 = *(const float4*)&As[kk * 132 + ty * 8 + 4];
            float4 bv  = *(const float4*)&Bs[kk * 68 + tx * 4];
            float a[8] = {av0.x, av0.y, av0.z, av0.w, av1.x, av1.y, av1.z, av1.w};
            float b[4] = {bv.x, bv.y, bv.z, bv.w};
#pragma unroll
            for (int i = 0; i < 8; i++)
#pragma unroll
                for (int j = 0; j < 4; j++) acc[i][j] += a[i] * b[j];
        }
        __syncthreads();
    }

#pragma unroll
    for (int i = 0; i < 8; i++) {
        float4 o = make_float4(acc[i][0], acc[i][1], acc[i][2], acc[i][3]);
        *(float4*)&C[(long)(m0 + ty * 8 + i) * GN + n0 + tx * 4] = o;
    }
}

// ---------------- feature map: z = x_head @ Wf[h], softmax over F ----------------
// grid (L/64, H, 2); z=0: Q->FQ with Wfq; z=1: K->FK with Wfk. 256 threads.
__global__ __launch_bounds__(256) void feature_kernel(
    const float* __restrict__ Q, const float* __restrict__ K,
    const float* __restrict__ Wfq, const float* __restrict__ Wfk,
    float* __restrict__ FQ, float* __restrict__ FK) {
    int h  = blockIdx.y;
    int l0 = blockIdx.x * 64;
    const float* src = (blockIdx.z == 0) ? Q : K;
    const float* Wf  = ((blockIdx.z == 0) ? Wfq : Wfk) + (long)h * HD * FD;
    float* dst       = ((blockIdx.z == 0) ? FQ : FK) + (long)h * L_SEQ * FD;

    __shared__ float qs[64 * 64];  // [row][d]
    __shared__ float ws[64 * 64];  // [d][f]
    int t = threadIdx.x;
#pragma unroll
    for (int r = 0; r < 16; r++) {
        int e = t + 256 * r;
        int row = e >> 6, col = e & 63;
        qs[e] = src[(long)(l0 + row) * HID + h * HD + col];
        ws[e] = Wf[e];
    }
    __syncthreads();

    int warp = t >> 5, lane = t & 31;
    float z0[8], z1[8];
#pragma unroll
    for (int r = 0; r < 8; r++) { z0[r] = 0.f; z1[r] = 0.f; }
    for (int d = 0; d < 64; d++) {
        float w0 = ws[d * 64 + lane];
        float w1 = ws[d * 64 + lane + 32];
#pragma unroll
        for (int r = 0; r < 8; r++) {
            float qv = qs[(warp * 8 + r) * 64 + d];
            z0[r] += qv * w0;
            z1[r] += qv * w1;
        }
    }
#pragma unroll
    for (int r = 0; r < 8; r++) {
        float m = fmaxf(z0[r], z1[r]);
#pragma unroll
        for (int o = 16; o > 0; o >>= 1) m = fmaxf(m, __shfl_xor_sync(0xffffffffu, m, o));
        float e0 = expf(z0[r] - m), e1 = expf(z1[r] - m);
        float s = e0 + e1;
#pragma unroll
        for (int o = 16; o > 0; o >>= 1) s += __shfl_xor_sync(0xffffffffu, s, o);
        float inv = 1.f / s;
        int l = l0 + warp * 8 + r;
        dst[(long)l * FD + lane]      = e0 * inv;
        dst[(long)l * FD + lane + 32] = e1 * inv;
    }
}

// ---------------- chunk sums: S[h,c,f,d] = sum_l fk*v ; KS[h,c,f] = sum_l fk -----
__global__ __launch_bounds__(256) void chunksum_kernel(
    const float* __restrict__ FK, const float* __restrict__ V,
    float* __restrict__ S, float* __restrict__ KS) {
    int c = blockIdx.x, h = blockIdx.y;
    __shared__ float fks[64 * 64];  // [l][f]
    __shared__ float vs[64 * 64];   // [l][d]
    int t = threadIdx.x;
#pragma unroll
    for (int r = 0; r < 16; r++) {
        int e = t + 256 * r;
        int row = e >> 6, col = e & 63;
        fks[e] = FK[(long)(h * L_SEQ + c * CS + row) * FD + col];
        vs[e]  = V[(long)(c * CS + row) * HID + h * HD + col];
    }
    __syncthreads();

    int d = t & 63, fg = t >> 6;
    float acc[16];
#pragma unroll
    for (int ff = 0; ff < 16; ff++) acc[ff] = 0.f;
    for (int l = 0; l < 64; l++) {
        float vv = vs[l * 64 + d];
#pragma unroll
        for (int ff = 0; ff < 16; ff++)
            acc[ff] += fks[l * 64 + fg * 16 + ff] * vv;
    }
    float* Sout = S + (long)(h * NC + c) * (FD * HD);
#pragma unroll
    for (int ff = 0; ff < 16; ff++)
        Sout[(fg * 16 + ff) * 64 + d] = acc[ff];

    if (t < 64) {
        float s = 0.f;
        for (int l = 0; l < 64; l++) s += fks[l * 64 + t];
        KS[(long)(h * NC + c) * FD + t] = s;
    }
}

// ---------------- exclusive prefix over chunks (in place) ------------------------
__global__ __launch_bounds__(256) void prefix_kernel(float* __restrict__ S,
                                                     float* __restrict__ KS) {
    int h = blockIdx.x, t = threadIdx.x;
    float run[16];
#pragma unroll
    for (int r = 0; r < 16; r++) run[r] = 0.f;
    for (int c = 0; c < NC; c++) {
        long base = (long)(h * NC + c) * (FD * HD);
#pragma unroll
        for (int r = 0; r < 16; r++) {
            int e = t + 256 * r;
            float* p = &S[base + e];
            float tmp = *p;
            *p = run[r];
            run[r] += tmp;
        }
    }
    if (t < 64) {
        float kr = 0.f;
        for (int c = 0; c < NC; c++) {
            float* p = &KS[(long)(h * NC + c) * FD + t];
            float tmp = *p;
            *p = kr;
            kr += tmp;
        }
    }
}

// ---------------- per-chunk output: intra (masked scores) + inter (prefix KV) ----
__global__ __launch_bounds__(256) void chunkout_kernel(
    const float* __restrict__ FQ, const float* __restrict__ FK,
    const float* __restrict__ V, const float* __restrict__ S,
    const float* __restrict__ KS, float* __restrict__ Y) {
    __shared__ float fqT[4096];  // fqT[f*64 + (i^f)]  (xor-swizzled transpose)
    __shared__ float buf[4096];  // fkT (swizzled) -> v[j][d] -> KV[f][d]
    __shared__ float At[4096];   // A^T masked [j][i]; later At[0..63] = denom

    int c = blockIdx.x, h = blockIdx.y;
    int t = threadIdx.x, lane = t & 31;

    const float* fqg = FQ + (long)(h * L_SEQ + c * CS) * FD;
    const float* fkg = FK + (long)(h * L_SEQ + c * CS) * FD;

#pragma unroll
    for (int r = 0; r < 16; r++) {
        int e = t + 256 * r;
        int i = e >> 6, f = e & 63;
        fqT[f * 64 + (i ^ f)] = fqg[e];
        buf[f * 64 + (i ^ f)] = fkg[e];
    }
    __syncthreads();

    // P1: A^T[j][i] = fq_i . fk_j, masked j<=i
    {
        int i = t & 63, jg = t >> 6;
        float a[16];
#pragma unroll
        for (int jj = 0; jj < 16; jj++) a[jj] = 0.f;
        for (int f = 0; f < 64; f++) {
            float qv = fqT[f * 64 + (i ^ f)];
#pragma unroll
            for (int jj = 0; jj < 16; jj++) {
                int j = jg * 16 + jj;
                a[jj] += qv * buf[f * 64 + (j ^ f)];
            }
        }
#pragma unroll
        for (int jj = 0; jj < 16; jj++) {
            int j = jg * 16 + jj;
            At[j * 64 + i] = (j <= i) ? a[jj] : 0.f;
        }
    }
    __syncthreads();

    // load v chunk (overwrites fk in buf)
    const float* vg = V + (long)(c * CS) * HID + h * HD;
#pragma unroll
    for (int r = 0; r < 16; r++) {
        int e = t + 256 * r;
        int j = e >> 6, d = e & 63;
        buf[e] = vg[(long)j * HID + d];
    }
    __syncthreads();

    // P2: y_intra[i][d] = sum_j A[i][j] * v[j][d]; denom for i=t<64
    int d = t & 63, ig = t >> 6;
    float y[16];
#pragma unroll
    for (int ii = 0; ii < 16; ii++) y[ii] = 0.f;
    for (int j = 0; j < 64; j++) {
        float vv = buf[j * 64 + d];
#pragma unroll
        for (int ii = 0; ii < 16; ii++)
            y[ii] += At[j * 64 + ig * 16 + ii] * vv;
    }
    float ds = 0.f;
    if (t < 64) {
        ds = 1e-12f;  // EPS
        const float* kb = KS + (long)(h * NC + c) * FD;
        float kp0 = kb[lane], kp1 = kb[lane + 32];
        for (int f = 0; f < 32; f++) {
            ds += fqT[f * 64 + (t ^ f)] * __shfl_sync(0xffffffffu, kp0, f);
            ds += fqT[(f + 32) * 64 + (t ^ (f + 32))] * __shfl_sync(0xffffffffu, kp1, f);
        }
        for (int j = 0; j < 64; j++) ds += At[j * 64 + t];  // rowsum of masked A
    }
    __syncthreads();

    // load KV prefix into buf; stash denom in At[0..63]
    const float* sg = S + (long)(h * NC + c) * (FD * HD);
#pragma unroll
    for (int r = 0; r < 16; r++) {
        int e = t + 256 * r;
        buf[e] = sg[e];  // [f][d]
    }
    if (t < 64) At[t] = ds;
    __syncthreads();

    // P3: y += fq_i . KV[:,d]; divide; store as [l][h*64+d]
    for (int f = 0; f < 64; f++) {
        float kvv = buf[f * 64 + d];
#pragma unroll
        for (int ii = 0; ii < 16; ii++)
            y[ii] += fqT[f * 64 + ((ig * 16 + ii) ^ f)] * kvv;
    }
    float* yg = Y + (long)(c * CS) * HID + h * HD;
#pragma unroll
    for (int ii = 0; ii < 16; ii++) {
        int i = ig * 16 + ii;
        yg[(long)i * HID + d] = y[ii] / At[i];
    }
}

// ---------------------------------- launch ---------------------------------------
extern "C" void kernel_launch(void* const* d_in, const int* in_sizes, int n_in,
                              void* d_out, int out_size) {
    (void)in_sizes; (void)n_in; (void)out_size;
    const float* hs  = (const float*)d_in[0];
    const float* Wq  = (const float*)d_in[1];
    const float* Wk  = (const float*)d_in[2];
    const float* Wv  = (const float*)d_in[3];
    const float* Wo  = (const float*)d_in[4];
    const float* Wfq = (const float*)d_in[5];
    const float* Wfk = (const float*)d_in[6];
    float* out = (float*)d_out;

    float *Qp, *Kp, *Vp, *FQp, *FKp, *Sp, *KSp, *Yp;
    cudaGetSymbolAddress((void**)&Qp,  g_Q);
    cudaGetSymbolAddress((void**)&Kp,  g_K);
    cudaGetSymbolAddress((void**)&Vp,  g_V);
    cudaGetSymbolAddress((void**)&FQp, g_FQ);
    cudaGetSymbolAddress((void**)&FKp, g_FK);
    cudaGetSymbolAddress((void**)&Sp,  g_S);
    cudaGetSymbolAddress((void**)&KSp, g_KS);
    cudaGetSymbolAddress((void**)&Yp,  g_Y);

    dim3 gemmGrid(GN / 64, L_SEQ / 128);

    sgemm_nt<<<gemmGrid, 256>>>(hs, Wq, Qp);
    sgemm_nt<<<gemmGrid, 256>>>(hs, Wk, Kp);
    sgemm_nt<<<gemmGrid, 256>>>(hs, Wv, Vp);

    feature_kernel<<<dim3(L_SEQ / 64, NH, 2), 256>>>(Qp, Kp, Wfq, Wfk, FQp, FKp);
    chunksum_kernel<<<dim3(NC, NH), 256>>>(FKp, Vp, Sp, KSp);
    prefix_kernel<<<NH, 256>>>(Sp, KSp);
    chunkout_kernel<<<dim3(NC, NH), 256>>>(FQp, FKp, Vp, Sp, KSp, Yp);

    sgemm_nt<<<gemmGrid, 256>>>(Yp, Wo, out);
}

// round 3
// speedup vs baseline: 2.1024x; 2.1024x over previous
#include <cuda_runtime.h>
#include <cuda_bf16.h>
#include <cstdint>

#define L_SEQ 1024
#define HID   2048
#define NH    32
#define HD    64
#define FD    64
#define NC    16
#define CS    64
#define GK    2048
#define GN    2048

// ---------------- scratch (device globals: no allocation allowed) ----------------
__device__ float g_Q [L_SEQ * HID];
__device__ float g_K [L_SEQ * HID];
__device__ float g_V [L_SEQ * HID];
__device__ float g_FQ[NH * L_SEQ * FD];
__device__ float g_FK[NH * L_SEQ * FD];
__device__ float g_S [NH * NC * FD * HD];
__device__ float g_KS[NH * NC * FD];
__device__ float g_Y [L_SEQ * HID];

// =============================== helpers ==========================================
__device__ __forceinline__ uint32_t smem_u32(const void* p) {
    uint32_t a;
    asm("{ .reg .u64 t; cvta.to.shared.u64 t, %1; cvt.u32.u64 %0, t; }" : "=r"(a) : "l"(p));
    return a;
}
__device__ __forceinline__ void ldsm4(uint32_t& r0, uint32_t& r1, uint32_t& r2, uint32_t& r3,
                                      uint32_t addr) {
    asm volatile("ldmatrix.sync.aligned.m8n8.x4.shared.b16 {%0,%1,%2,%3}, [%4];"
                 : "=r"(r0), "=r"(r1), "=r"(r2), "=r"(r3) : "r"(addr));
}
__device__ __forceinline__ void mma16816(float* c, const uint32_t* a, const uint32_t* b) {
    asm volatile(
        "mma.sync.aligned.m16n8k16.row.col.f32.bf16.bf16.f32 "
        "{%0,%1,%2,%3}, {%4,%5,%6,%7}, {%8,%9}, {%0,%1,%2,%3};"
        : "+f"(c[0]), "+f"(c[1]), "+f"(c[2]), "+f"(c[3])
        : "r"(a[0]), "r"(a[1]), "r"(a[2]), "r"(a[3]), "r"(b[0]), "r"(b[1]));
}

// Split fp32x4 -> packed bf16 hi (uint2) and lo (uint2)
__device__ __forceinline__ void split4(float4 v, uint2& hp, uint2& lp) {
    __nv_bfloat16 h0 = __float2bfloat16_rn(v.x);
    __nv_bfloat16 h1 = __float2bfloat16_rn(v.y);
    __nv_bfloat16 h2 = __float2bfloat16_rn(v.z);
    __nv_bfloat16 h3 = __float2bfloat16_rn(v.w);
    __nv_bfloat16 l0 = __float2bfloat16_rn(v.x - __bfloat162float(h0));
    __nv_bfloat16 l1 = __float2bfloat16_rn(v.y - __bfloat162float(h1));
    __nv_bfloat16 l2 = __float2bfloat16_rn(v.z - __bfloat162float(h2));
    __nv_bfloat16 l3 = __float2bfloat16_rn(v.w - __bfloat162float(h3));
    hp.x = (uint32_t)__bfloat16_as_ushort(h0) | ((uint32_t)__bfloat16_as_ushort(h1) << 16);
    hp.y = (uint32_t)__bfloat16_as_ushort(h2) | ((uint32_t)__bfloat16_as_ushort(h3) << 16);
    lp.x = (uint32_t)__bfloat16_as_ushort(l0) | ((uint32_t)__bfloat16_as_ushort(l1) << 16);
    lp.y = (uint32_t)__bfloat16_as_ushort(l2) | ((uint32_t)__bfloat16_as_ushort(l3) << 16);
}

// ================== bf16x3 HMMA GEMM: C[M,N] = A[M,K] @ B[N,K]^T ===================
// 128x128x32 CTA tile, 8 warps (2x4), warp 64x32, double-buffered SMEM,
// in-kernel fp32 -> bf16 hi/lo split, fp32 accumulate of 3 products.
// Rows stored with 80-byte stride: 16B-aligned, conflict-free LDSM phases.
#define ROWB   80                       // bytes per 32-elem bf16 row (padded)
#define TILEB  (128 * ROWB)             // 10240 B per tile
#define STAGEB (4 * TILEB)              // Ahi,Alo,Bhi,Blo = 40960 B
#define GEMM_SMEM (2 * STAGEB)          // 81920 B

__global__ __launch_bounds__(256, 1) void gemm_bf16x3(
    const float* __restrict__ A,
    const float* __restrict__ B0, const float* __restrict__ B1, const float* __restrict__ B2,
    float* __restrict__ C0, float* __restrict__ C1, float* __restrict__ C2) {
    extern __shared__ char smem[];
    const uint32_t sb = smem_u32(smem);

    const int t = threadIdx.x, wid = t >> 5, lane = t & 31;
    const int wsel = blockIdx.x >> 4;
    const int n0 = (blockIdx.x & 15) * 128;
    const int m0 = blockIdx.y * 128;
    const float* B = (wsel == 0) ? B0 : (wsel == 1) ? B1 : B2;
    float* C       = (wsel == 0) ? C0 : (wsel == 1) ? C1 : C2;

    const int wm0 = (wid >> 2) * 64;   // warp m offset in tile
    const int wn0 = (wid & 3) * 32;    // warp n offset in tile

    // GMEM staging addresses: id = t + 256*r ; row=id>>3, c4=(id&7)*4
    const int grow = t >> 3;          // base row (r adds 32 rows)
    const int gcol = (t & 7) * 4;

    float4 stA[4], stB[4];
#pragma unroll
    for (int r = 0; r < 4; r++) {
        stA[r] = *(const float4*)(A + (long)(m0 + grow + 32 * r) * GK + gcol);
        stB[r] = *(const float4*)(B + (long)(n0 + grow + 32 * r) * GK + gcol);
    }

    float acc[4][4][4];
#pragma unroll
    for (int i = 0; i < 4; i++)
#pragma unroll
        for (int j = 0; j < 4; j++)
#pragma unroll
            for (int k = 0; k < 4; k++) acc[i][j][k] = 0.f;

    const int g  = lane >> 3;   // ldmatrix lane group
    const int lr = lane & 7;

    for (int it = 0; it < GK / 32; it++) {
        const int st = it & 1;
        char* dst = smem + st * STAGEB;
        // convert + STS (stage st)
#pragma unroll
        for (int r = 0; r < 4; r++) {
            int row = grow + 32 * r;
            int bo = row * ROWB + (t & 7) * 8;
            uint2 hp, lp;
            split4(stA[r], hp, lp);
            *(uint2*)(dst + bo) = hp;
            *(uint2*)(dst + TILEB + bo) = lp;
            split4(stB[r], hp, lp);
            *(uint2*)(dst + 2 * TILEB + bo) = hp;
            *(uint2*)(dst + 3 * TILEB + bo) = lp;
        }
        // prefetch next chunk into registers (latency hidden by MMA section)
        if (it + 1 < GK / 32) {
            int k0 = (it + 1) * 32;
#pragma unroll
            for (int r = 0; r < 4; r++) {
                stA[r] = *(const float4*)(A + (long)(m0 + grow + 32 * r) * GK + k0 + gcol);
                stB[r] = *(const float4*)(B + (long)(n0 + grow + 32 * r) * GK + k0 + gcol);
            }
        }
        __syncthreads();

        const uint32_t ahi = sb + st * STAGEB;
        const uint32_t alo = ahi + TILEB;
        const uint32_t bhi = ahi + 2 * TILEB;
        const uint32_t blo = ahi + 3 * TILEB;

#pragma unroll
        for (int ks = 0; ks < 2; ks++) {
            // B fragments: 4 n8-tiles (hi & lo)
            uint32_t bh[4][2], bl[4][2];
#pragma unroll
            for (int nt2 = 0; nt2 < 2; nt2++) {
                int row = wn0 + nt2 * 16 + (g >> 1) * 8 + lr;
                int kc  = ks * 16 + (g & 1) * 8;
                uint32_t off = (uint32_t)(row * ROWB + kc * 2);
                ldsm4(bh[nt2 * 2][0], bh[nt2 * 2][1], bh[nt2 * 2 + 1][0], bh[nt2 * 2 + 1][1],
                      bhi + off);
                ldsm4(bl[nt2 * 2][0], bl[nt2 * 2][1], bl[nt2 * 2 + 1][0], bl[nt2 * 2 + 1][1],
                      blo + off);
            }
#pragma unroll
            for (int mt = 0; mt < 4; mt++) {
                int row = wm0 + mt * 16 + (g & 1) * 8 + lr;
                int kc  = ks * 16 + (g >> 1) * 8;
                uint32_t off = (uint32_t)(row * ROWB + kc * 2);
                uint32_t ah[4], al[4];
                ldsm4(ah[0], ah[1], ah[2], ah[3], ahi + off);
                ldsm4(al[0], al[1], al[2], al[3], alo + off);
#pragma unroll
                for (int nt = 0; nt < 4; nt++) {
                    mma16816(acc[mt][nt], ah, bh[nt]);  // hi*hi
                    mma16816(acc[mt][nt], ah, bl[nt]);  // hi*lo
                    mma16816(acc[mt][nt], al, bh[nt]);  // lo*hi
                }
            }
        }
        __syncthreads();
    }

    // Epilogue: direct float2 stores
    const int gid = lane >> 2, tig = lane & 3;
#pragma unroll
    for (int mt = 0; mt < 4; mt++) {
#pragma unroll
        for (int nt = 0; nt < 4; nt++) {
            int row = m0 + wm0 + mt * 16 + gid;
            int col = n0 + wn0 + nt * 8 + tig * 2;
            *(float2*)(C + (long)row * GN + col) =
                make_float2(acc[mt][nt][0], acc[mt][nt][1]);
            *(float2*)(C + (long)(row + 8) * GN + col) =
                make_float2(acc[mt][nt][2], acc[mt][nt][3]);
        }
    }
}

// ---------------- feature map: z = x_head @ Wf[h], softmax over F ----------------
__global__ __launch_bounds__(256) void feature_kernel(
    const float* __restrict__ Q, const float* __restrict__ K,
    const float* __restrict__ Wfq, const float* __restrict__ Wfk,
    float* __restrict__ FQ, float* __restrict__ FK) {
    int h  = blockIdx.y;
    int l0 = blockIdx.x * 64;
    const float* src = (blockIdx.z == 0) ? Q : K;
    const float* Wf  = ((blockIdx.z == 0) ? Wfq : Wfk) + (long)h * HD * FD;
    float* dst       = ((blockIdx.z == 0) ? FQ : FK) + (long)h * L_SEQ * FD;

    __shared__ float qs[64 * 64];
    __shared__ float ws[64 * 64];
    int t = threadIdx.x;
#pragma unroll
    for (int r = 0; r < 16; r++) {
        int e = t + 256 * r;
        int row = e >> 6, col = e & 63;
        qs[e] = src[(long)(l0 + row) * HID + h * HD + col];
        ws[e] = Wf[e];
    }
    __syncthreads();

    int warp = t >> 5, lane = t & 31;
    float z0[8], z1[8];
#pragma unroll
    for (int r = 0; r < 8; r++) { z0[r] = 0.f; z1[r] = 0.f; }
    for (int d = 0; d < 64; d++) {
        float w0 = ws[d * 64 + lane];
        float w1 = ws[d * 64 + lane + 32];
#pragma unroll
        for (int r = 0; r < 8; r++) {
            float qv = qs[(warp * 8 + r) * 64 + d];
            z0[r] += qv * w0;
            z1[r] += qv * w1;
        }
    }
#pragma unroll
    for (int r = 0; r < 8; r++) {
        float m = fmaxf(z0[r], z1[r]);
#pragma unroll
        for (int o = 16; o > 0; o >>= 1) m = fmaxf(m, __shfl_xor_sync(0xffffffffu, m, o));
        float e0 = expf(z0[r] - m), e1 = expf(z1[r] - m);
        float s = e0 + e1;
#pragma unroll
        for (int o = 16; o > 0; o >>= 1) s += __shfl_xor_sync(0xffffffffu, s, o);
        float inv = 1.f / s;
        int l = l0 + warp * 8 + r;
        dst[(long)l * FD + lane]      = e0 * inv;
        dst[(long)l * FD + lane + 32] = e1 * inv;
    }
}

// ---------------- chunk sums ------------------------------------------------------
__global__ __launch_bounds__(256) void chunksum_kernel(
    const float* __restrict__ FK, const float* __restrict__ V,
    float* __restrict__ S, float* __restrict__ KS) {
    int c = blockIdx.x, h = blockIdx.y;
    __shared__ float fks[64 * 64];
    __shared__ float vs[64 * 64];
    int t = threadIdx.x;
#pragma unroll
    for (int r = 0; r < 16; r++) {
        int e = t + 256 * r;
        int row = e >> 6, col = e & 63;
        fks[e] = FK[(long)(h * L_SEQ + c * CS + row) * FD + col];
        vs[e]  = V[(long)(c * CS + row) * HID + h * HD + col];
    }
    __syncthreads();

    int d = t & 63, fg = t >> 6;
    float acc[16];
#pragma unroll
    for (int ff = 0; ff < 16; ff++) acc[ff] = 0.f;
    for (int l = 0; l < 64; l++) {
        float vv = vs[l * 64 + d];
#pragma unroll
        for (int ff = 0; ff < 16; ff++)
            acc[ff] += fks[l * 64 + fg * 16 + ff] * vv;
    }
    float* Sout = S + (long)(h * NC + c) * (FD * HD);
#pragma unroll
    for (int ff = 0; ff < 16; ff++)
        Sout[(fg * 16 + ff) * 64 + d] = acc[ff];

    if (t < 64) {
        float s = 0.f;
        for (int l = 0; l < 64; l++) s += fks[l * 64 + t];
        KS[(long)(h * NC + c) * FD + t] = s;
    }
}

// ---------------- exclusive prefix over chunks ------------------------------------
__global__ __launch_bounds__(256) void prefix_kernel(float* __restrict__ S,
                                                     float* __restrict__ KS) {
    int h = blockIdx.x, t = threadIdx.x;
    float run[16];
#pragma unroll
    for (int r = 0; r < 16; r++) run[r] = 0.f;
    for (int c = 0; c < NC; c++) {
        long base = (long)(h * NC + c) * (FD * HD);
#pragma unroll
        for (int r = 0; r < 16; r++) {
            int e = t + 256 * r;
            float* p = &S[base + e];
            float tmp = *p;
            *p = run[r];
            run[r] += tmp;
        }
    }
    if (t < 64) {
        float kr = 0.f;
        for (int c = 0; c < NC; c++) {
            float* p = &KS[(long)(h * NC + c) * FD + t];
            float tmp = *p;
            *p = kr;
            kr += tmp;
        }
    }
}

// ---------------- per-chunk output ------------------------------------------------
__global__ __launch_bounds__(256) void chunkout_kernel(
    const float* __restrict__ FQ, const float* __restrict__ FK,
    const float* __restrict__ V, const float* __restrict__ S,
    const float* __restrict__ KS, float* __restrict__ Y) {
    __shared__ float fqT[4096];
    __shared__ float buf[4096];
    __shared__ float At[4096];

    int c = blockIdx.x, h = blockIdx.y;
    int t = threadIdx.x, lane = t & 31;

    const float* fqg = FQ + (long)(h * L_SEQ + c * CS) * FD;
    const float* fkg = FK + (long)(h * L_SEQ + c * CS) * FD;

#pragma unroll
    for (int r = 0; r < 16; r++) {
        int e = t + 256 * r;
        int i = e >> 6, f = e & 63;
        fqT[f * 64 + (i ^ f)] = fqg[e];
        buf[f * 64 + (i ^ f)] = fkg[e];
    }
    __syncthreads();

    {
        int i = t & 63, jg = t >> 6;
        float a[16];
#pragma unroll
        for (int jj = 0; jj < 16; jj++) a[jj] = 0.f;
        for (int f = 0; f < 64; f++) {
            float qv = fqT[f * 64 + (i ^ f)];
#pragma unroll
            for (int jj = 0; jj < 16; jj++) {
                int j = jg * 16 + jj;
                a[jj] += qv * buf[f * 64 + (j ^ f)];
            }
        }
#pragma unroll
        for (int jj = 0; jj < 16; jj++) {
            int j = jg * 16 + jj;
            At[j * 64 + i] = (j <= i) ? a[jj] : 0.f;
        }
    }
    __syncthreads();

    const float* vg = V + (long)(c * CS) * HID + h * HD;
#pragma unroll
    for (int r = 0; r < 16; r++) {
        int e = t + 256 * r;
        int j = e >> 6, d = e & 63;
        buf[e] = vg[(long)j * HID + d];
    }
    __syncthreads();

    int d = t & 63, ig = t >> 6;
    float y[16];
#pragma unroll
    for (int ii = 0; ii < 16; ii++) y[ii] = 0.f;
    for (int j = 0; j < 64; j++) {
        float vv = buf[j * 64 + d];
#pragma unroll
        for (int ii = 0; ii < 16; ii++)
            y[ii] += At[j * 64 + ig * 16 + ii] * vv;
    }
    float ds = 0.f;
    if (t < 64) {
        ds = 1e-12f;
        const float* kb = KS + (long)(h * NC + c) * FD;
        float kp0 = kb[lane], kp1 = kb[lane + 32];
        for (int f = 0; f < 32; f++) {
            ds += fqT[f * 64 + (t ^ f)] * __shfl_sync(0xffffffffu, kp0, f);
            ds += fqT[(f + 32) * 64 + (t ^ (f + 32))] * __shfl_sync(0xffffffffu, kp1, f);
        }
        for (int j = 0; j < 64; j++) ds += At[j * 64 + t];
    }
    __syncthreads();

    const float* sg = S + (long)(h * NC + c) * (FD * HD);
#pragma unroll
    for (int r = 0; r < 16; r++) {
        int e = t + 256 * r;
        buf[e] = sg[e];
    }
    if (t < 64) At[t] = ds;
    __syncthreads();

    for (int f = 0; f < 64; f++) {
        float kvv = buf[f * 64 + d];
#pragma unroll
        for (int ii = 0; ii < 16; ii++)
            y[ii] += fqT[f * 64 + ((ig * 16 + ii) ^ f)] * kvv;
    }
    float* yg = Y + (long)(c * CS) * HID + h * HD;
#pragma unroll
    for (int ii = 0; ii < 16; ii++) {
        int i = ig * 16 + ii;
        yg[(long)i * HID + d] = y[ii] / At[i];
    }
}

// ---------------------------------- launch ---------------------------------------
extern "C" void kernel_launch(void* const* d_in, const int* in_sizes, int n_in,
                              void* d_out, int out_size) {
    (void)in_sizes; (void)n_in; (void)out_size;
    const float* hs  = (const float*)d_in[0];
    const float* Wq  = (const float*)d_in[1];
    const float* Wk  = (const float*)d_in[2];
    const float* Wv  = (const float*)d_in[3];
    const float* Wo  = (const float*)d_in[4];
    const float* Wfq = (const float*)d_in[5];
    const float* Wfk = (const float*)d_in[6];
    float* out = (float*)d_out;

    float *Qp, *Kp, *Vp, *FQp, *FKp, *Sp, *KSp, *Yp;
    cudaGetSymbolAddress((void**)&Qp,  g_Q);
    cudaGetSymbolAddress((void**)&Kp,  g_K);
    cudaGetSymbolAddress((void**)&Vp,  g_V);
    cudaGetSymbolAddress((void**)&FQp, g_FQ);
    cudaGetSymbolAddress((void**)&FKp, g_FK);
    cudaGetSymbolAddress((void**)&Sp,  g_S);
    cudaGetSymbolAddress((void**)&KSp, g_KS);
    cudaGetSymbolAddress((void**)&Yp,  g_Y);

    cudaFuncSetAttribute(gemm_bf16x3, cudaFuncAttributeMaxDynamicSharedMemorySize, GEMM_SMEM);

    // fused Q/K/V projection: grid.x = 3*16 n-tiles
    gemm_bf16x3<<<dim3(48, 8), 256, GEMM_SMEM>>>(hs, Wq, Wk, Wv, Qp, Kp, Vp);

    feature_kernel<<<dim3(L_SEQ / 64, NH, 2), 256>>>(Qp, Kp, Wfq, Wfk, FQp, FKp);
    chunksum_kernel<<<dim3(NC, NH), 256>>>(FKp, Vp, Sp, KSp);
    prefix_kernel<<<NH, 256>>>(Sp, KSp);
    chunkout_kernel<<<dim3(NC, NH), 256>>>(FQp, FKp, Vp, Sp, KSp, Yp);

    // output projection
    gemm_bf16x3<<<dim3(16, 8), 256, GEMM_SMEM>>>(Yp, Wo, Wo, Wo, out, out, out);
}